// round 1
// baseline (speedup 1.0000x reference)
#include <cuda_runtime.h>
#include <math.h>

// Problem constants
#define VV    32768      // voxels = 32*32*32
#define NSEQ  1024       // sequences per branch
#define LSEQ  32         // sequence length
#define CD    128        // channel dim
#define DIc   256        // inner dim

// ---------------- scratch (device globals: allocation-free) ----------------
__device__ float g_xn  [(size_t)VV * CD];          // 16 MB   normalized x, [vox][C]
__device__ float g_xz  [3ull * VV * 512];          // 201 MB  in_proj out, [r][n][t][512]
__device__ float g_xc  [3ull * VV * DIc];          // 100 MB  conv+silu,   [r][n][t][256]
__device__ float g_dbl [3ull * VV * 40];           // 16 MB   x_proj out,  [r][n][t][40]
__device__ float g_ymid[3ull * VV * DIc];          // 100 MB  scan out,    [r][n][t][256]
__device__ float g_yb  [(size_t)VV * 384];         // 50 MB   cat [vox][3*128]
__device__ float g_f   [(size_t)VV * CD];          // 16 MB   gelu(fusion)

// branch (r) sequence (n,t) -> voxel index (d*1024 + h*32 + w)
__device__ __forceinline__ int vox_of(int r, int m) {
    int n = m >> 5, t = m & 31;
    if (r == 0) return (t << 10) + n;                              // axial: n=h*32+w, t=d
    if (r == 1) return ((n >> 5) << 10) + (t << 5) + (n & 31);     // coronal: n=d*32+w, t=h
    return (n << 5) + t;                                           // sagittal: n=d*32+h, t=w
}

// ---------------- LayerNorm over channels, write [vox][C] ----------------
__global__ __launch_bounds__(256) void ln_kernel(
    const float* __restrict__ x, const float* __restrict__ g, const float* __restrict__ b)
{
    __shared__ float sm[128][33];
    __shared__ float smu[32], srs[32];
    const int v0 = blockIdx.x * 32;
    const int tid = threadIdx.x;

    #pragma unroll
    for (int it = 0; it < 16; it++) {
        int e = it * 256 + tid;
        int c = e >> 5, vi = e & 31;
        sm[c][vi] = x[(size_t)c * VV + v0 + vi];
    }
    __syncthreads();
    if (tid < 32) {
        float s = 0.f, s2 = 0.f;
        #pragma unroll 8
        for (int c = 0; c < 128; c++) { float v = sm[c][tid]; s += v; s2 += v * v; }
        float m = s * (1.f / 128.f);
        float var = s2 * (1.f / 128.f) - m * m;
        smu[tid] = m;
        srs[tid] = rsqrtf(var + 1e-5f);
    }
    __syncthreads();
    #pragma unroll
    for (int it = 0; it < 16; it++) {
        int e = it * 256 + tid;
        int c = e & 127, vi = e >> 7;
        float v = (sm[c][vi] - smu[vi]) * srs[vi] * g[c] + b[c];
        g_xn[(size_t)(v0 + vi) * 128 + c] = v;
    }
}

// ---------------- generic tiled GEMM:  C = A @ W^T  (both operands [rows][K]) ----
// MODE 0: x_proj   A=g_xc[r],  B=x_proj_w[r] (40x256)  -> g_dbl[r]
// MODE 1: in_proj  A=g_xn gathered by branch map, B=in_proj_w[r] (512x128) -> g_xz[r]
// MODE 2: out_proj A=g_ymid[r], B=out_proj_w[r] (128x256) -> scatter g_yb[vox][r*128+j]
// MODE 3: fusion   A=g_yb (K=384), B=fusion_w (128x384), +bias, gelu -> g_f
// MODE 4: proj     A=proj_w (M=128,K=128), B=g_f (N=V), +bias +residual -> out[c][vox]
template <int MODE>
__global__ __launch_bounds__(256) void gemm_kernel(
    const float* __restrict__ W, const float* __restrict__ bias,
    const float* __restrict__ resid, float* __restrict__ outp)
{
    constexpr int BM = 64, BN = 64, BK = 16;
    constexpr int Kc = (MODE == 1) ? 128 : (MODE == 3) ? 384 : (MODE == 4) ? 128 : 256;
    constexpr int Nc = (MODE == 1) ? 512 : (MODE == 0) ? 40 : (MODE == 4) ? VV : 128;

    __shared__ float As[BK][BM + 4];
    __shared__ float Bs[BK][BN + 4];

    const int r  = blockIdx.z;
    const int m0 = blockIdx.y * BM;
    const int j0 = blockIdx.x * BN;
    const int tid = threadIdx.x;
    const int tx = tid & 15, ty = tid >> 4;

    const float* Abase = nullptr;
    const float* Bbase = nullptr;
    if (MODE == 0)      { Abase = g_xc   + (size_t)r * VV * 256; Bbase = W + (size_t)r * 40 * 256; }
    else if (MODE == 1) { Abase = g_xn;                          Bbase = W + (size_t)r * 512 * 128; }
    else if (MODE == 2) { Abase = g_ymid + (size_t)r * VV * 256; Bbase = W + (size_t)r * 128 * 256; }
    else if (MODE == 3) { Abase = g_yb;                          Bbase = W; }
    else                { Abase = W;                             Bbase = g_f; }

    const int lrow = tid >> 2;         // 0..63
    const int lk4  = (tid & 3) << 2;   // 0,4,8,12

    // A row pointer (gathered for MODE 1)
    const int am = m0 + lrow;
    const float* arow;
    if (MODE == 1) arow = g_xn + (size_t)vox_of(r, am) * 128;
    else           arow = Abase + (size_t)am * Kc;

    const int bj = j0 + lrow;
    const float* brow = Bbase + (size_t)bj * Kc;
    const bool bvalid = (Nc % BN == 0) || (bj < Nc);

    float acc[4][4];
    #pragma unroll
    for (int i = 0; i < 4; i++)
        #pragma unroll
        for (int j = 0; j < 4; j++) acc[i][j] = 0.f;

    for (int k0 = 0; k0 < Kc; k0 += BK) {
        float4 av = *(const float4*)(arow + k0 + lk4);
        float4 bv = bvalid ? *(const float4*)(brow + k0 + lk4) : make_float4(0.f, 0.f, 0.f, 0.f);
        As[lk4 + 0][lrow] = av.x; As[lk4 + 1][lrow] = av.y;
        As[lk4 + 2][lrow] = av.z; As[lk4 + 3][lrow] = av.w;
        Bs[lk4 + 0][lrow] = bv.x; Bs[lk4 + 1][lrow] = bv.y;
        Bs[lk4 + 2][lrow] = bv.z; Bs[lk4 + 3][lrow] = bv.w;
        __syncthreads();
        #pragma unroll
        for (int k = 0; k < BK; k++) {
            float4 a = *(const float4*)&As[k][ty << 2];
            float4 b = *(const float4*)&Bs[k][tx << 2];
            acc[0][0] += a.x * b.x; acc[0][1] += a.x * b.y; acc[0][2] += a.x * b.z; acc[0][3] += a.x * b.w;
            acc[1][0] += a.y * b.x; acc[1][1] += a.y * b.y; acc[1][2] += a.y * b.z; acc[1][3] += a.y * b.w;
            acc[2][0] += a.z * b.x; acc[2][1] += a.z * b.y; acc[2][2] += a.z * b.z; acc[2][3] += a.z * b.w;
            acc[3][0] += a.w * b.x; acc[3][1] += a.w * b.y; acc[3][2] += a.w * b.z; acc[3][3] += a.w * b.w;
        }
        __syncthreads();
    }

    #pragma unroll
    for (int i = 0; i < 4; i++) {
        const int m = m0 + (ty << 2) + i;
        int vox = 0;
        if (MODE == 2) vox = vox_of(r, m);
        #pragma unroll
        for (int j = 0; j < 4; j++) {
            const int jj = j0 + (tx << 2) + j;
            const float v = acc[i][j];
            if (MODE == 0) {
                if (jj < 40) g_dbl[(size_t)r * VV * 40 + (size_t)m * 40 + jj] = v;
            } else if (MODE == 1) {
                g_xz[((size_t)r * VV + m) * 512 + jj] = v;
            } else if (MODE == 2) {
                g_yb[(size_t)vox * 384 + r * 128 + jj] = v;
            } else if (MODE == 3) {
                float u = v + bias[jj];
                g_f[(size_t)m * 128 + jj] = 0.5f * u * (1.f + erff(u * 0.70710678118654752f));
            } else {
                outp[(size_t)m * VV + jj] = v + bias[m] + resid[(size_t)m * VV + jj];
            }
        }
    }
}

// ---------------- causal depthwise conv (k=4) + bias + silu ----------------
__global__ __launch_bounds__(256) void conv_kernel(
    const float* __restrict__ conv_w, const float* __restrict__ conv_b)
{
    const int r = blockIdx.y, n = blockIdx.x, di = threadIdx.x;
    const float* xzp = g_xz + ((size_t)(r * NSEQ + n) * LSEQ) * 512 + di;
    float*       xcp = g_xc + ((size_t)(r * NSEQ + n) * LSEQ) * 256 + di;
    const int wb = (r * 256 + di) * 4;
    const float w0 = conv_w[wb + 0], w1 = conv_w[wb + 1], w2 = conv_w[wb + 2], w3 = conv_w[wb + 3];
    const float cb = conv_b[r * 256 + di];

    float xv[35];
    xv[0] = 0.f; xv[1] = 0.f; xv[2] = 0.f;
    #pragma unroll
    for (int t = 0; t < 32; t++) xv[t + 3] = xzp[(size_t)t * 512];
    #pragma unroll
    for (int t = 0; t < 32; t++) {
        float s = xv[t] * w0 + xv[t + 1] * w1 + xv[t + 2] * w2 + xv[t + 3] * w3 + cb;
        xcp[(size_t)t * 256] = s / (1.f + __expf(-s));   // silu
    }
}

// ---------------- dt + selective scan + gate, fused ----------------
__global__ __launch_bounds__(256) void scan_kernel(
    const float* __restrict__ dt_w, const float* __restrict__ dt_b,
    const float* __restrict__ A_log, const float* __restrict__ Dparam)
{
    __shared__ float sm[LSEQ * 40];
    const int r = blockIdx.y, n = blockIdx.x, di = threadIdx.x;

    const float* dblp = g_dbl + (size_t)(r * NSEQ + n) * LSEQ * 40;
    for (int e = di; e < LSEQ * 40; e += 256) sm[e] = dblp[e];
    __syncthreads();

    float dtw[8];
    #pragma unroll
    for (int k = 0; k < 8; k++) dtw[k] = dt_w[(r * 256 + di) * 8 + k];
    const float dtb = dt_b[r * 256 + di];
    const float Dpv = Dparam[r * 256 + di];

    float Av[16];
    #pragma unroll
    for (int s = 0; s < 16; s++) Av[s] = -__expf(A_log[(r * 256 + di) * 16 + s]);
    // arithmetic-progression fast path check (A[s] ~= (s+1)*A[0])
    bool ap = true;
    #pragma unroll
    for (int s = 1; s < 16; s++)
        ap = ap && (fabsf(Av[s] - (float)(s + 1) * Av[0]) <= 1e-4f * fabsf(Av[s]) + 1e-6f);

    float h[16];
    #pragma unroll
    for (int s = 0; s < 16; s++) h[s] = 0.f;

    const float* xcp = g_xc   + ((size_t)(r * NSEQ + n) * LSEQ) * 256 + di;
    const float* zp  = g_xz   + ((size_t)(r * NSEQ + n) * LSEQ) * 512 + 256 + di;
    float*       yp  = g_ymid + ((size_t)(r * NSEQ + n) * LSEQ) * 256 + di;

    for (int t = 0; t < LSEQ; t++) {
        const float* row = sm + t * 40;
        float xl = dtb;
        #pragma unroll
        for (int k = 0; k < 8; k++) xl += row[k] * dtw[k];
        const float dt = (xl > 15.f) ? xl : log1pf(__expf(xl));  // softplus

        const float xcv = xcp[(size_t)t * 256];
        const float zv  = zp [(size_t)t * 512];
        const float du  = dt * xcv;
        float y = 0.f;

        if (ap) {
            const float p = __expf(dt * Av[0]);
            float dAk = p;
            #pragma unroll
            for (int s = 0; s < 16; s++) {
                h[s] = dAk * h[s] + du * row[8 + s];
                y += h[s] * row[24 + s];
                dAk *= p;
            }
        } else {
            #pragma unroll
            for (int s = 0; s < 16; s++) {
                const float dA = __expf(dt * Av[s]);
                h[s] = dA * h[s] + du * row[8 + s];
                y += h[s] * row[24 + s];
            }
        }
        const float sz = zv / (1.f + __expf(-zv));   // silu(z)
        yp[(size_t)t * 256] = (y + Dpv * xcv) * sz;
    }
}

// ---------------- launch ----------------
extern "C" void kernel_launch(void* const* d_in, const int* in_sizes, int n_in,
                              void* d_out, int out_size)
{
    const float* x      = (const float*)d_in[0];
    const float* ng     = (const float*)d_in[1];
    const float* nb     = (const float*)d_in[2];
    const float* in_w   = (const float*)d_in[3];
    const float* conv_w = (const float*)d_in[4];
    const float* conv_b = (const float*)d_in[5];
    const float* xp_w   = (const float*)d_in[6];
    const float* dt_w   = (const float*)d_in[7];
    const float* dt_b   = (const float*)d_in[8];
    const float* A_log  = (const float*)d_in[9];
    const float* Dparam = (const float*)d_in[10];
    const float* out_w  = (const float*)d_in[11];
    const float* fw     = (const float*)d_in[12];
    const float* fb     = (const float*)d_in[13];
    const float* pw     = (const float*)d_in[14];
    const float* pb     = (const float*)d_in[15];
    float* out = (float*)d_out;

    ln_kernel<<<VV / 32, 256>>>(x, ng, nb);
    gemm_kernel<1><<<dim3(512 / 64, VV / 64, 3), 256>>>(in_w, nullptr, nullptr, nullptr);   // in_proj
    conv_kernel<<<dim3(NSEQ, 3), 256>>>(conv_w, conv_b);
    gemm_kernel<0><<<dim3(1, VV / 64, 3), 256>>>(xp_w, nullptr, nullptr, nullptr);          // x_proj
    scan_kernel<<<dim3(NSEQ, 3), 256>>>(dt_w, dt_b, A_log, Dparam);
    gemm_kernel<2><<<dim3(128 / 64, VV / 64, 3), 256>>>(out_w, nullptr, nullptr, nullptr);  // out_proj
    gemm_kernel<3><<<dim3(128 / 64, VV / 64, 1), 256>>>(fw, fb, nullptr, nullptr);          // fusion+gelu
    gemm_kernel<4><<<dim3(VV / 64, 128 / 64, 1), 256>>>(pw, pb, x, out);                    // proj+residual
}

// round 3
// speedup vs baseline: 2.3989x; 2.3989x over previous
#include <cuda_runtime.h>
#include <cuda_bf16.h>
#include <cstdint>
#include <math.h>

typedef unsigned int u32;

#define VV    32768
#define NSEQ  1024
#define LSEQ  32
#define CD    128
#define DIc   256

typedef __nv_bfloat16 bf16;

// ---------------- scratch (device globals: allocation-free) ----------------
__device__ __align__(16) bf16  g_xn  [(size_t)VV * CD];       // normalized x, [vox][C]
__device__ __align__(16) bf16  g_xz  [3ull * VV * 512];       // in_proj out, [r][n][t][512]
__device__ __align__(16) bf16  g_xc  [3ull * VV * DIc];       // conv+silu,   [r][n][t][256]
__device__ __align__(16) float g_dbl [3ull * VV * 40];        // x_proj out,  [r][n][t][40]
__device__ __align__(16) bf16  g_ymid[3ull * VV * DIc];       // scan out,    [r][n][t][256]
__device__ __align__(16) bf16  g_yb  [(size_t)VV * 384];      // cat [vox][3*128]
__device__ __align__(16) bf16  g_f   [(size_t)VV * CD];       // gelu(fusion) [vox][128]

// bf16 weights
__device__ __align__(16) bf16 g_w_in [3 * 512 * 128];
__device__ __align__(16) bf16 g_w_xp [3 * 40 * 256];
__device__ __align__(16) bf16 g_w_out[3 * 128 * 256];
__device__ __align__(16) bf16 g_w_f  [128 * 384];
__device__ __align__(16) bf16 g_w_p  [128 * 128];

// branch (r) sequence (n,t) -> voxel index (d*1024 + h*32 + w)
__device__ __forceinline__ int vox_of(int r, int m) {
    int n = m >> 5, t = m & 31;
    if (r == 0) return (t << 10) + n;                              // axial
    if (r == 1) return ((n >> 5) << 10) + (t << 5) + (n & 31);     // coronal
    return (n << 5) + t;                                           // sagittal
}

// ---------------- weight convert fp32 -> bf16 ----------------
__global__ __launch_bounds__(256) void cvt_kernel(
    const float* __restrict__ in_w, const float* __restrict__ xp_w,
    const float* __restrict__ out_w, const float* __restrict__ fw,
    const float* __restrict__ pw)
{
    const int i = blockIdx.x * 256 + threadIdx.x;
    if (i < 3 * 512 * 128) g_w_in[i]  = __float2bfloat16(in_w[i]);
    if (i < 3 * 40 * 256)  g_w_xp[i]  = __float2bfloat16(xp_w[i]);
    if (i < 3 * 128 * 256) g_w_out[i] = __float2bfloat16(out_w[i]);
    if (i < 128 * 384)     g_w_f[i]   = __float2bfloat16(fw[i]);
    if (i < 128 * 128)     g_w_p[i]   = __float2bfloat16(pw[i]);
}

// ---------------- LayerNorm over channels, write bf16 [vox][C] ----------------
__global__ __launch_bounds__(256) void ln_kernel(
    const float* __restrict__ x, const float* __restrict__ g, const float* __restrict__ b)
{
    __shared__ float sm[128][33];
    __shared__ float smu[32], srs[32];
    const int v0 = blockIdx.x * 32;
    const int tid = threadIdx.x;

    #pragma unroll
    for (int it = 0; it < 16; it++) {
        int e = it * 256 + tid;
        int c = e >> 5, vi = e & 31;
        sm[c][vi] = x[(size_t)c * VV + v0 + vi];
    }
    __syncthreads();
    if (tid < 32) {
        float s = 0.f, s2 = 0.f;
        #pragma unroll 8
        for (int c = 0; c < 128; c++) { float v = sm[c][tid]; s += v; s2 += v * v; }
        float m = s * (1.f / 128.f);
        float var = s2 * (1.f / 128.f) - m * m;
        smu[tid] = m;
        srs[tid] = rsqrtf(var + 1e-5f);
    }
    __syncthreads();
    #pragma unroll
    for (int it = 0; it < 16; it++) {
        int e = it * 256 + tid;
        int c = e & 127, vi = e >> 7;
        float v = (sm[c][vi] - smu[vi]) * srs[vi] * g[c] + b[c];
        g_xn[(size_t)(v0 + vi) * 128 + c] = __float2bfloat16(v);
    }
}

// ---------------- tensor-core helpers ----------------
__device__ __forceinline__ void ldsm4(u32* r, const void* p) {
    u32 addr = (u32)__cvta_generic_to_shared(p);
    asm volatile("ldmatrix.sync.aligned.m8n8.x4.shared.b16 {%0,%1,%2,%3}, [%4];"
        : "=r"(r[0]), "=r"(r[1]), "=r"(r[2]), "=r"(r[3]) : "r"(addr));
}
__device__ __forceinline__ void mma16816(float* c, const u32* a, u32 b0, u32 b1) {
    asm volatile("mma.sync.aligned.m16n8k16.row.col.f32.bf16.bf16.f32 "
        "{%0,%1,%2,%3}, {%4,%5,%6,%7}, {%8,%9}, {%0,%1,%2,%3};"
        : "+f"(c[0]), "+f"(c[1]), "+f"(c[2]), "+f"(c[3])
        : "r"(a[0]), "r"(a[1]), "r"(a[2]), "r"(a[3]), "r"(b0), "r"(b1));
}

// ---------------- bf16 tensor-core GEMM:  C = A @ W^T ----------------
// MODE 0: x_proj   A=g_xc[r](bf16), B=g_w_xp[r](40x256)   -> g_dbl (fp32)
// MODE 1: in_proj  A=g_xn gathered, B=g_w_in[r](512x128)  -> g_xz (bf16)
// MODE 2: out_proj A=g_ymid[r],     B=g_w_out[r](128x256) -> scatter g_yb (bf16)
// MODE 3: fusion   A=g_yb (K=384),  B=g_w_f(128x384), +bias, gelu -> g_f (bf16)
// MODE 4: proj     A=g_w_p(128x128),B=g_f (N=VV), +bias +residual -> out (fp32)
template <int MODE>
__global__ __launch_bounds__(256) void bgemm_kernel(
    const float* __restrict__ bias, const float* __restrict__ resid, float* __restrict__ outp)
{
    constexpr int Kc = (MODE == 1) ? 128 : (MODE == 3) ? 384 : (MODE == 4) ? 128 : 256;
    constexpr int Nc = (MODE == 1) ? 512 : (MODE == 0) ? 40 : (MODE == 4) ? VV : 128;

    __shared__ bf16 As[128][40];
    __shared__ bf16 Bs[64][40];

    const int r   = blockIdx.z;
    const int m0  = blockIdx.y * 128;
    const int j0  = blockIdx.x * 64;
    const int tid = threadIdx.x;
    const int lane = tid & 31, warp = tid >> 5;
    const int wm = (warp & 3) * 32, wn = (warp >> 2) * 32;

    const bf16* Abase = nullptr;
    const bf16* Bbase = nullptr;
    if (MODE == 0)      { Abase = g_xc   + (size_t)r * VV * 256; Bbase = g_w_xp  + (size_t)r * 40 * 256; }
    else if (MODE == 1) { Abase = g_xn;                          Bbase = g_w_in  + (size_t)r * 512 * 128; }
    else if (MODE == 2) { Abase = g_ymid + (size_t)r * VV * 256; Bbase = g_w_out + (size_t)r * 128 * 256; }
    else if (MODE == 3) { Abase = g_yb;                          Bbase = g_w_f; }
    else                { Abase = g_w_p;                         Bbase = g_f; }

    const int lrow = tid >> 2;         // 0..63
    const int lk8  = (tid & 3) << 3;   // 0,8,16,24

    const bf16 *arow0, *arow1;
    if (MODE == 1) {
        arow0 = g_xn + (size_t)vox_of(r, m0 + lrow) * 128;
        arow1 = g_xn + (size_t)vox_of(r, m0 + lrow + 64) * 128;
    } else {
        arow0 = Abase + (size_t)(m0 + lrow) * Kc;
        arow1 = Abase + (size_t)(m0 + lrow + 64) * Kc;
    }
    const int bj = j0 + lrow;
    const bf16* brow = Bbase + (size_t)bj * Kc;
    const bool bvalid = (Nc % 64 == 0) || (bj < Nc);

    float acc[2][4][4];
    #pragma unroll
    for (int f = 0; f < 2; f++)
        #pragma unroll
        for (int n = 0; n < 4; n++)
            #pragma unroll
            for (int i = 0; i < 4; i++) acc[f][n][i] = 0.f;

    const int srow = lane & 15;
    const int scol = (lane >> 4) << 3;

    for (int k0 = 0; k0 < Kc; k0 += 32) {
        uint4 av0 = *(const uint4*)(arow0 + k0 + lk8);
        uint4 av1 = *(const uint4*)(arow1 + k0 + lk8);
        uint4 bv  = bvalid ? *(const uint4*)(brow + k0 + lk8) : make_uint4(0, 0, 0, 0);
        __syncthreads();
        *(uint4*)&As[lrow     ][lk8] = av0;
        *(uint4*)&As[lrow + 64][lk8] = av1;
        *(uint4*)&Bs[lrow     ][lk8] = bv;
        __syncthreads();
        #pragma unroll
        for (int kk = 0; kk < 32; kk += 16) {
            u32 a[2][4], b[2][4];
            ldsm4(a[0], &As[wm +      srow][kk + scol]);
            ldsm4(a[1], &As[wm + 16 + srow][kk + scol]);
            ldsm4(b[0], &Bs[wn +      srow][kk + scol]);
            ldsm4(b[1], &Bs[wn + 16 + srow][kk + scol]);
            #pragma unroll
            for (int f = 0; f < 2; f++)
                #pragma unroll
                for (int n = 0; n < 4; n++)
                    mma16816(acc[f][n], a[f], b[n >> 1][n & 1], b[n >> 1][(n & 1) + 2]);
        }
    }

    // ---- epilogue ----
    const int grp = lane >> 2, tg = lane & 3;
    #pragma unroll
    for (int f = 0; f < 2; f++) {
        #pragma unroll
        for (int half = 0; half < 2; half++) {
            const int m = m0 + wm + f * 16 + grp + half * 8;
            int vox = 0;
            if (MODE == 2) vox = vox_of(r, m);
            #pragma unroll
            for (int n = 0; n < 4; n++) {
                const int j = j0 + wn + n * 8 + tg * 2;
                const float c0 = acc[f][n][half * 2 + 0];
                const float c1 = acc[f][n][half * 2 + 1];
                if (MODE == 0) {
                    if (j < 40)
                        *(float2*)&g_dbl[(size_t)r * VV * 40 + (size_t)m * 40 + j] = make_float2(c0, c1);
                } else if (MODE == 1) {
                    __nv_bfloat162 v; v.x = __float2bfloat16(c0); v.y = __float2bfloat16(c1);
                    *(__nv_bfloat162*)&g_xz[((size_t)r * VV + m) * 512 + j] = v;
                } else if (MODE == 2) {
                    __nv_bfloat162 v; v.x = __float2bfloat16(c0); v.y = __float2bfloat16(c1);
                    *(__nv_bfloat162*)&g_yb[(size_t)vox * 384 + r * 128 + j] = v;
                } else if (MODE == 3) {
                    float u0 = c0 + bias[j], u1 = c1 + bias[j + 1];
                    float gl0 = 0.5f * u0 * (1.f + erff(u0 * 0.70710678118654752f));
                    float gl1 = 0.5f * u1 * (1.f + erff(u1 * 0.70710678118654752f));
                    __nv_bfloat162 v; v.x = __float2bfloat16(gl0); v.y = __float2bfloat16(gl1);
                    *(__nv_bfloat162*)&g_f[(size_t)m * 128 + j] = v;
                } else {
                    float2 rd = *(const float2*)&resid[(size_t)m * VV + j];
                    *(float2*)&outp[(size_t)m * VV + j] =
                        make_float2(c0 + bias[m] + rd.x, c1 + bias[m] + rd.y);
                }
            }
        }
    }
}

// ---------------- causal depthwise conv (k=4) + bias + silu ----------------
__global__ __launch_bounds__(256) void conv_kernel(
    const float* __restrict__ conv_w, const float* __restrict__ conv_b)
{
    const int r = blockIdx.y, n = blockIdx.x, di = threadIdx.x;
    const bf16* xzp = g_xz + ((size_t)(r * NSEQ + n) * LSEQ) * 512 + di;
    bf16*       xcp = g_xc + ((size_t)(r * NSEQ + n) * LSEQ) * 256 + di;
    const int wb = (r * 256 + di) * 4;
    const float w0 = conv_w[wb + 0], w1 = conv_w[wb + 1], w2 = conv_w[wb + 2], w3 = conv_w[wb + 3];
    const float cb = conv_b[r * 256 + di];

    float xv[35];
    xv[0] = 0.f; xv[1] = 0.f; xv[2] = 0.f;
    #pragma unroll
    for (int t = 0; t < 32; t++) xv[t + 3] = __bfloat162float(xzp[(size_t)t * 512]);
    #pragma unroll
    for (int t = 0; t < 32; t++) {
        float s = xv[t] * w0 + xv[t + 1] * w1 + xv[t + 2] * w2 + xv[t + 3] * w3 + cb;
        xcp[(size_t)t * 256] = __float2bfloat16(s / (1.f + __expf(-s)));
    }
}

// ---------------- dt + selective scan + gate, fused ----------------
__global__ __launch_bounds__(256) void scan_kernel(
    const float* __restrict__ dt_w, const float* __restrict__ dt_b,
    const float* __restrict__ A_log, const float* __restrict__ Dparam)
{
    __shared__ float sm[LSEQ * 40];
    const int r = blockIdx.y, n = blockIdx.x, di = threadIdx.x;

    const float* dblp = g_dbl + (size_t)(r * NSEQ + n) * LSEQ * 40;
    for (int e = di; e < LSEQ * 40; e += 256) sm[e] = dblp[e];
    __syncthreads();

    float dtw[8];
    #pragma unroll
    for (int k = 0; k < 8; k++) dtw[k] = dt_w[(r * 256 + di) * 8 + k];
    const float dtb = dt_b[r * 256 + di];
    const float Dpv = Dparam[r * 256 + di];

    float Av[16];
    #pragma unroll
    for (int s = 0; s < 16; s++) Av[s] = -__expf(A_log[(r * 256 + di) * 16 + s]);
    bool ap = true;
    #pragma unroll
    for (int s = 1; s < 16; s++)
        ap = ap && (fabsf(Av[s] - (float)(s + 1) * Av[0]) <= 1e-4f * fabsf(Av[s]) + 1e-6f);

    float h[16];
    #pragma unroll
    for (int s = 0; s < 16; s++) h[s] = 0.f;

    const bf16* xcp = g_xc   + ((size_t)(r * NSEQ + n) * LSEQ) * 256 + di;
    const bf16* zp  = g_xz   + ((size_t)(r * NSEQ + n) * LSEQ) * 512 + 256 + di;
    bf16*       yp  = g_ymid + ((size_t)(r * NSEQ + n) * LSEQ) * 256 + di;

    for (int t = 0; t < LSEQ; t++) {
        const float* row = sm + t * 40;
        float xl = dtb;
        #pragma unroll
        for (int k = 0; k < 8; k++) xl += row[k] * dtw[k];
        const float dt = (xl > 15.f) ? xl : log1pf(__expf(xl));

        const float xcv = __bfloat162float(xcp[(size_t)t * 256]);
        const float zv  = __bfloat162float(zp [(size_t)t * 512]);
        const float du  = dt * xcv;
        float y = 0.f;

        if (ap) {
            const float p = __expf(dt * Av[0]);
            float dAk = p;
            #pragma unroll
            for (int s = 0; s < 16; s++) {
                h[s] = dAk * h[s] + du * row[8 + s];
                y += h[s] * row[24 + s];
                dAk *= p;
            }
        } else {
            #pragma unroll
            for (int s = 0; s < 16; s++) {
                const float dA = __expf(dt * Av[s]);
                h[s] = dA * h[s] + du * row[8 + s];
                y += h[s] * row[24 + s];
            }
        }
        const float sz = zv / (1.f + __expf(-zv));
        yp[(size_t)t * 256] = __float2bfloat16((y + Dpv * xcv) * sz);
    }
}

// ---------------- launch ----------------
extern "C" void kernel_launch(void* const* d_in, const int* in_sizes, int n_in,
                              void* d_out, int out_size)
{
    const float* x      = (const float*)d_in[0];
    const float* ng     = (const float*)d_in[1];
    const float* nb     = (const float*)d_in[2];
    const float* in_w   = (const float*)d_in[3];
    const float* conv_w = (const float*)d_in[4];
    const float* conv_b = (const float*)d_in[5];
    const float* xp_w   = (const float*)d_in[6];
    const float* dt_w   = (const float*)d_in[7];
    const float* dt_b   = (const float*)d_in[8];
    const float* A_log  = (const float*)d_in[9];
    const float* Dparam = (const float*)d_in[10];
    const float* out_w  = (const float*)d_in[11];
    const float* fw     = (const float*)d_in[12];
    const float* fb     = (const float*)d_in[13];
    const float* pw     = (const float*)d_in[14];
    const float* pb     = (const float*)d_in[15];
    float* out = (float*)d_out;

    cvt_kernel<<<(3 * 512 * 128 + 255) / 256, 256>>>(in_w, xp_w, out_w, fw, pw);
    ln_kernel<<<VV / 32, 256>>>(x, ng, nb);
    bgemm_kernel<1><<<dim3(8, VV / 128, 3), 256>>>(nullptr, nullptr, nullptr);   // in_proj
    conv_kernel<<<dim3(NSEQ, 3), 256>>>(conv_w, conv_b);
    bgemm_kernel<0><<<dim3(1, VV / 128, 3), 256>>>(nullptr, nullptr, nullptr);   // x_proj
    scan_kernel<<<dim3(NSEQ, 3), 256>>>(dt_w, dt_b, A_log, Dparam);
    bgemm_kernel<2><<<dim3(2, VV / 128, 3), 256>>>(nullptr, nullptr, nullptr);   // out_proj
    bgemm_kernel<3><<<dim3(2, VV / 128, 1), 256>>>(fb, nullptr, nullptr);        // fusion+gelu
    bgemm_kernel<4><<<dim3(VV / 64, 1, 1), 256>>>(pb, x, out);                   // proj+residual
}

// round 4
// speedup vs baseline: 2.7985x; 1.1666x over previous
#include <cuda_runtime.h>
#include <cuda_bf16.h>
#include <cstdint>
#include <math.h>

typedef unsigned int u32;

#define VV    32768
#define NSEQ  1024
#define LSEQ  32
#define CD    128
#define DIc   256

typedef __nv_bfloat16 bf16;

// ---------------- scratch (device globals: allocation-free) ----------------
__device__ __align__(16) bf16  g_xn  [(size_t)VV * CD];       // normalized x, [vox][C]
__device__ __align__(16) bf16  g_z   [3ull * VV * DIc];       // silu(z),     [r][n][t][256]
__device__ __align__(16) bf16  g_xc  [3ull * VV * DIc];       // conv+silu,   [r][n][t][256]
__device__ __align__(16) float g_dbl [3ull * VV * 40];        // x_proj out,  [r][n][t][40]
__device__ __align__(16) bf16  g_ymid[3ull * VV * DIc];       // scan out,    [r][n][t][256]
__device__ __align__(16) bf16  g_yb  [(size_t)VV * 384];      // cat [vox][3*128]
__device__ __align__(16) bf16  g_f   [(size_t)VV * CD];       // gelu(fusion) [vox][128]

// bf16 weights
__device__ __align__(16) bf16 g_w_in [3 * 512 * 128];
__device__ __align__(16) bf16 g_w_xp [3 * 40 * 256];
__device__ __align__(16) bf16 g_w_out[3 * 128 * 256];
__device__ __align__(16) bf16 g_w_f  [128 * 384];
__device__ __align__(16) bf16 g_w_p  [128 * 128];

// branch (r) sequence (n,t) -> voxel index (d*1024 + h*32 + w)
__device__ __forceinline__ int vox_of(int r, int m) {
    int n = m >> 5, t = m & 31;
    if (r == 0) return (t << 10) + n;                              // axial
    if (r == 1) return ((n >> 5) << 10) + (t << 5) + (n & 31);     // coronal
    return (n << 5) + t;                                           // sagittal
}

// ---------------- weight convert fp32 -> bf16 ----------------
__global__ __launch_bounds__(256) void cvt_kernel(
    const float* __restrict__ in_w, const float* __restrict__ xp_w,
    const float* __restrict__ out_w, const float* __restrict__ fw,
    const float* __restrict__ pw)
{
    const int i = blockIdx.x * 256 + threadIdx.x;
    if (i < 3 * 512 * 128) g_w_in[i]  = __float2bfloat16(in_w[i]);
    if (i < 3 * 40 * 256)  g_w_xp[i]  = __float2bfloat16(xp_w[i]);
    if (i < 3 * 128 * 256) g_w_out[i] = __float2bfloat16(out_w[i]);
    if (i < 128 * 384)     g_w_f[i]   = __float2bfloat16(fw[i]);
    if (i < 128 * 128)     g_w_p[i]   = __float2bfloat16(pw[i]);
}

// ---------------- LayerNorm over channels, write bf16 [vox][C] ----------------
__global__ __launch_bounds__(256) void ln_kernel(
    const float* __restrict__ x, const float* __restrict__ g, const float* __restrict__ b)
{
    __shared__ float sm[128][33];
    __shared__ float smu[32], srs[32];
    const int v0 = blockIdx.x * 32;
    const int tid = threadIdx.x;

    #pragma unroll
    for (int it = 0; it < 16; it++) {
        int e = it * 256 + tid;
        int c = e >> 5, vi = e & 31;
        sm[c][vi] = x[(size_t)c * VV + v0 + vi];
    }
    __syncthreads();
    if (tid < 32) {
        float s = 0.f, s2 = 0.f;
        #pragma unroll 8
        for (int c = 0; c < 128; c++) { float v = sm[c][tid]; s += v; s2 += v * v; }
        float m = s * (1.f / 128.f);
        float var = s2 * (1.f / 128.f) - m * m;
        smu[tid] = m;
        srs[tid] = rsqrtf(var + 1e-5f);
    }
    __syncthreads();
    #pragma unroll
    for (int it = 0; it < 16; it++) {
        int e = it * 256 + tid;
        int c = e & 127, vi = e >> 7;
        float v = (sm[c][vi] - smu[vi]) * srs[vi] * g[c] + b[c];
        g_xn[(size_t)(v0 + vi) * 128 + c] = __float2bfloat16(v);
    }
}

// ---------------- tensor-core / async-copy helpers ----------------
__device__ __forceinline__ void ldsm4(u32* r, const void* p) {
    u32 addr = (u32)__cvta_generic_to_shared(p);
    asm volatile("ldmatrix.sync.aligned.m8n8.x4.shared.b16 {%0,%1,%2,%3}, [%4];"
        : "=r"(r[0]), "=r"(r[1]), "=r"(r[2]), "=r"(r[3]) : "r"(addr));
}
__device__ __forceinline__ void mma16816(float* c, const u32* a, u32 b0, u32 b1) {
    asm volatile("mma.sync.aligned.m16n8k16.row.col.f32.bf16.bf16.f32 "
        "{%0,%1,%2,%3}, {%4,%5,%6,%7}, {%8,%9}, {%0,%1,%2,%3};"
        : "+f"(c[0]), "+f"(c[1]), "+f"(c[2]), "+f"(c[3])
        : "r"(a[0]), "r"(a[1]), "r"(a[2]), "r"(a[3]), "r"(b0), "r"(b1));
}
__device__ __forceinline__ void cpa16(void* dst, const void* src, bool pred) {
    u32 d = (u32)__cvta_generic_to_shared(dst);
    int sz = pred ? 16 : 0;
    asm volatile("cp.async.ca.shared.global [%0], [%1], 16, %2;" :: "r"(d), "l"(src), "r"(sz));
}
__device__ __forceinline__ void cpa_commit() { asm volatile("cp.async.commit_group;"); }
template <int N> __device__ __forceinline__ void cpa_wait() {
    asm volatile("cp.async.wait_group %0;" :: "n"(N));
}
__device__ __forceinline__ float siluf(float s) { return s / (1.f + __expf(-s)); }

// ---------------- bf16 tensor-core GEMM:  C = A @ W^T ----------------
// MODE 0: x_proj   A=g_xc[r],      B=g_w_xp[r](40x256)   -> g_dbl (fp32)
// MODE 1: in_proj  A=g_xn gathered,B=g_w_in[r](512x128)  -> epilogue conv+silu -> g_xc / silu -> g_z
// MODE 2: out_proj A=g_ymid[r],    B=g_w_out[r](128x256) -> scatter g_yb (bf16)
// MODE 3: fusion   A=g_yb (K=384), B=g_w_f(128x384), +bias, gelu -> g_f (bf16)
// MODE 4: proj     A=g_w_p,        B=g_f (N=VV), +bias +residual -> out (fp32)
template <int MODE>
__global__ __launch_bounds__(256) void bgemm_kernel(
    const float* __restrict__ bias, const float* __restrict__ resid, float* __restrict__ outp,
    const float* __restrict__ conv_w, const float* __restrict__ conv_b)
{
    constexpr int Kc = (MODE == 1) ? 128 : (MODE == 3) ? 384 : (MODE == 4) ? 128 : 256;
    constexpr int Nc = (MODE == 1) ? 512 : (MODE == 0) ? 40 : (MODE == 4) ? VV : 128;
    constexpr int NSTAGE = Kc / 32;

    __shared__ __align__(16) bf16 As[2][128][40];
    __shared__ __align__(16) bf16 Bs[2][64][40];

    const int r   = blockIdx.z;
    const int m0  = blockIdx.y * 128;
    const int j0  = blockIdx.x * 64;
    const int tid = threadIdx.x;
    const int lane = tid & 31, warp = tid >> 5;
    const int wm = (warp & 3) * 32, wn = (warp >> 2) * 32;

    const bf16* Abase = nullptr;
    const bf16* Bbase = nullptr;
    if (MODE == 0)      { Abase = g_xc   + (size_t)r * VV * 256; Bbase = g_w_xp  + (size_t)r * 40 * 256; }
    else if (MODE == 1) { Abase = g_xn;                          Bbase = g_w_in  + (size_t)r * 512 * 128; }
    else if (MODE == 2) { Abase = g_ymid + (size_t)r * VV * 256; Bbase = g_w_out + (size_t)r * 128 * 256; }
    else if (MODE == 3) { Abase = g_yb;                          Bbase = g_w_f; }
    else                { Abase = g_w_p;                         Bbase = g_f; }

    const int lrow = tid >> 2;         // 0..63
    const int lk8  = (tid & 3) << 3;   // 0,8,16,24

    const bf16 *arow0, *arow1;
    if (MODE == 1) {
        arow0 = g_xn + (size_t)vox_of(r, m0 + lrow) * 128;
        arow1 = g_xn + (size_t)vox_of(r, m0 + lrow + 64) * 128;
    } else {
        arow0 = Abase + (size_t)(m0 + lrow) * Kc;
        arow1 = Abase + (size_t)(m0 + lrow + 64) * Kc;
    }
    const int bj = j0 + lrow;
    const bf16* brow = Bbase + (size_t)bj * Kc;
    const bool bvalid = (Nc % 64 == 0) || (bj < Nc);

    float acc[2][4][4];
    #pragma unroll
    for (int f = 0; f < 2; f++)
        #pragma unroll
        for (int n = 0; n < 4; n++)
            #pragma unroll
            for (int i = 0; i < 4; i++) acc[f][n][i] = 0.f;

    const int srow = lane & 15;
    const int scol = (lane >> 4) << 3;

    // prologue: stage 0
    cpa16(&As[0][lrow     ][lk8], arow0 + lk8, true);
    cpa16(&As[0][lrow + 64][lk8], arow1 + lk8, true);
    cpa16(&Bs[0][lrow     ][lk8], brow  + lk8, bvalid);
    cpa_commit();

    int sb = 0;
    #pragma unroll
    for (int st = 0; st < NSTAGE; st++) {
        const int kn = (st + 1) * 32;
        if (kn < Kc) {
            cpa16(&As[sb ^ 1][lrow     ][lk8], arow0 + kn + lk8, true);
            cpa16(&As[sb ^ 1][lrow + 64][lk8], arow1 + kn + lk8, true);
            cpa16(&Bs[sb ^ 1][lrow     ][lk8], brow  + kn + lk8, bvalid);
        }
        cpa_commit();
        cpa_wait<1>();
        __syncthreads();
        #pragma unroll
        for (int kk = 0; kk < 32; kk += 16) {
            u32 a[2][4], b[2][4];
            ldsm4(a[0], &As[sb][wm +      srow][kk + scol]);
            ldsm4(a[1], &As[sb][wm + 16 + srow][kk + scol]);
            ldsm4(b[0], &Bs[sb][wn +      srow][kk + scol]);
            ldsm4(b[1], &Bs[sb][wn + 16 + srow][kk + scol]);
            #pragma unroll
            for (int f = 0; f < 2; f++)
                #pragma unroll
                for (int n = 0; n < 4; n++)
                    mma16816(acc[f][n], a[f], b[n >> 1][n & 1], b[n >> 1][(n & 1) + 2]);
        }
        __syncthreads();
        sb ^= 1;
    }

    // ---- epilogue ----
    const int grp = lane >> 2, tg = lane & 3;

    if (MODE == 1) {
        // in_proj: xp half -> stage + causal conv + silu -> g_xc ; z half -> silu -> g_z
        __shared__ bf16 Cs[128][72];
        if (j0 < 256) {
            #pragma unroll
            for (int f = 0; f < 2; f++)
                #pragma unroll
                for (int half = 0; half < 2; half++) {
                    const int mm = wm + f * 16 + grp + half * 8;
                    #pragma unroll
                    for (int n = 0; n < 4; n++) {
                        const int jj = wn + n * 8 + tg * 2;
                        Cs[mm][jj]     = __float2bfloat16(acc[f][n][half * 2 + 0]);
                        Cs[mm][jj + 1] = __float2bfloat16(acc[f][n][half * 2 + 1]);
                    }
                }
            __syncthreads();
            const int c = tid & 63, sq = tid >> 6;
            const int gdi = j0 + c;
            const int wb = (r * 256 + gdi) * 4;
            const float w0 = conv_w[wb], w1 = conv_w[wb + 1], w2 = conv_w[wb + 2], w3 = conv_w[wb + 3];
            const float cb = conv_b[r * 256 + gdi];
            float x0 = 0.f, x1 = 0.f, x2 = 0.f;
            bf16* dst = g_xc + ((size_t)r * VV + m0 + sq * 32) * 256 + gdi;
            #pragma unroll
            for (int t = 0; t < 32; t++) {
                const float xv = __bfloat162float(Cs[sq * 32 + t][c]);
                const float s = x0 * w0 + x1 * w1 + x2 * w2 + xv * w3 + cb;
                dst[(size_t)t * 256] = __float2bfloat16(siluf(s));
                x0 = x1; x1 = x2; x2 = xv;
            }
        } else {
            #pragma unroll
            for (int f = 0; f < 2; f++)
                #pragma unroll
                for (int half = 0; half < 2; half++) {
                    const int m = m0 + wm + f * 16 + grp + half * 8;
                    #pragma unroll
                    for (int n = 0; n < 4; n++) {
                        const int j = j0 - 256 + wn + n * 8 + tg * 2;
                        __nv_bfloat162 v;
                        v.x = __float2bfloat16(siluf(acc[f][n][half * 2 + 0]));
                        v.y = __float2bfloat16(siluf(acc[f][n][half * 2 + 1]));
                        *(__nv_bfloat162*)&g_z[((size_t)r * VV + m) * 256 + j] = v;
                    }
                }
        }
        return;
    }

    #pragma unroll
    for (int f = 0; f < 2; f++) {
        #pragma unroll
        for (int half = 0; half < 2; half++) {
            const int m = m0 + wm + f * 16 + grp + half * 8;
            int vox = 0;
            if (MODE == 2) vox = vox_of(r, m);
            #pragma unroll
            for (int n = 0; n < 4; n++) {
                const int j = j0 + wn + n * 8 + tg * 2;
                const float c0 = acc[f][n][half * 2 + 0];
                const float c1 = acc[f][n][half * 2 + 1];
                if (MODE == 0) {
                    if (j < 40)
                        *(float2*)&g_dbl[(size_t)r * VV * 40 + (size_t)m * 40 + j] = make_float2(c0, c1);
                } else if (MODE == 2) {
                    __nv_bfloat162 v; v.x = __float2bfloat16(c0); v.y = __float2bfloat16(c1);
                    *(__nv_bfloat162*)&g_yb[(size_t)vox * 384 + r * 128 + j] = v;
                } else if (MODE == 3) {
                    float u0 = c0 + bias[j], u1 = c1 + bias[j + 1];
                    float gl0 = 0.5f * u0 * (1.f + erff(u0 * 0.70710678118654752f));
                    float gl1 = 0.5f * u1 * (1.f + erff(u1 * 0.70710678118654752f));
                    __nv_bfloat162 v; v.x = __float2bfloat16(gl0); v.y = __float2bfloat16(gl1);
                    *(__nv_bfloat162*)&g_f[(size_t)m * 128 + j] = v;
                } else {
                    float2 rd = *(const float2*)&resid[(size_t)m * VV + j];
                    *(float2*)&outp[(size_t)m * VV + j] =
                        make_float2(c0 + bias[m] + rd.x, c1 + bias[m] + rd.y);
                }
            }
        }
    }
}

// ---------------- dt + selective scan + gate, fused ----------------
__global__ __launch_bounds__(256) void scan_kernel(
    const float* __restrict__ dt_w, const float* __restrict__ dt_b,
    const float* __restrict__ A_log, const float* __restrict__ Dparam)
{
    __shared__ float sm[LSEQ * 40];
    const int r = blockIdx.y, n = blockIdx.x, di = threadIdx.x;

    const float* dblp = g_dbl + (size_t)(r * NSEQ + n) * LSEQ * 40;
    for (int e = di; e < LSEQ * 40; e += 256) sm[e] = dblp[e];
    __syncthreads();

    float dtw[8];
    #pragma unroll
    for (int k = 0; k < 8; k++) dtw[k] = dt_w[(r * 256 + di) * 8 + k];
    const float dtb = dt_b[r * 256 + di];
    const float Dpv = Dparam[r * 256 + di];

    float Av[16];
    #pragma unroll
    for (int s = 0; s < 16; s++) Av[s] = -__expf(A_log[(r * 256 + di) * 16 + s]);
    bool ap = true;
    #pragma unroll
    for (int s = 1; s < 16; s++)
        ap = ap && (fabsf(Av[s] - (float)(s + 1) * Av[0]) <= 1e-4f * fabsf(Av[s]) + 1e-6f);

    float h[16];
    #pragma unroll
    for (int s = 0; s < 16; s++) h[s] = 0.f;

    const bf16* xcp = g_xc   + ((size_t)(r * NSEQ + n) * LSEQ) * 256 + di;
    const bf16* zp  = g_z    + ((size_t)(r * NSEQ + n) * LSEQ) * 256 + di;
    bf16*       yp  = g_ymid + ((size_t)(r * NSEQ + n) * LSEQ) * 256 + di;

    for (int t = 0; t < LSEQ; t++) {
        const float* row = sm + t * 40;
        float xl = dtb;
        #pragma unroll
        for (int k = 0; k < 8; k++) xl += row[k] * dtw[k];
        const float dt = (xl > 15.f) ? xl : log1pf(__expf(xl));

        const float xcv = __bfloat162float(xcp[(size_t)t * 256]);
        const float sz  = __bfloat162float(zp [(size_t)t * 256]);   // pre-silu'ed
        const float du  = dt * xcv;
        float y = 0.f;

        if (ap) {
            const float p = __expf(dt * Av[0]);
            float dAk = p;
            #pragma unroll
            for (int s = 0; s < 16; s++) {
                h[s] = dAk * h[s] + du * row[8 + s];
                y += h[s] * row[24 + s];
                dAk *= p;
            }
        } else {
            #pragma unroll
            for (int s = 0; s < 16; s++) {
                const float dA = __expf(dt * Av[s]);
                h[s] = dA * h[s] + du * row[8 + s];
                y += h[s] * row[24 + s];
            }
        }
        yp[(size_t)t * 256] = __float2bfloat16((y + Dpv * xcv) * sz);
    }
}

// ---------------- launch ----------------
extern "C" void kernel_launch(void* const* d_in, const int* in_sizes, int n_in,
                              void* d_out, int out_size)
{
    const float* x      = (const float*)d_in[0];
    const float* ng     = (const float*)d_in[1];
    const float* nb     = (const float*)d_in[2];
    const float* in_w   = (const float*)d_in[3];
    const float* conv_w = (const float*)d_in[4];
    const float* conv_b = (const float*)d_in[5];
    const float* xp_w   = (const float*)d_in[6];
    const float* dt_w   = (const float*)d_in[7];
    const float* dt_b   = (const float*)d_in[8];
    const float* A_log  = (const float*)d_in[9];
    const float* Dparam = (const float*)d_in[10];
    const float* out_w  = (const float*)d_in[11];
    const float* fw     = (const float*)d_in[12];
    const float* fb     = (const float*)d_in[13];
    const float* pw     = (const float*)d_in[14];
    const float* pb     = (const float*)d_in[15];
    float* out = (float*)d_out;

    cvt_kernel<<<(3 * 512 * 128 + 255) / 256, 256>>>(in_w, xp_w, out_w, fw, pw);
    ln_kernel<<<VV / 32, 256>>>(x, ng, nb);
    bgemm_kernel<1><<<dim3(8, VV / 128, 3), 256>>>(nullptr, nullptr, nullptr, conv_w, conv_b); // in_proj+conv+silu
    bgemm_kernel<0><<<dim3(1, VV / 128, 3), 256>>>(nullptr, nullptr, nullptr, nullptr, nullptr); // x_proj
    scan_kernel<<<dim3(NSEQ, 3), 256>>>(dt_w, dt_b, A_log, Dparam);
    bgemm_kernel<2><<<dim3(2, VV / 128, 3), 256>>>(nullptr, nullptr, nullptr, nullptr, nullptr); // out_proj
    bgemm_kernel<3><<<dim3(2, VV / 128, 1), 256>>>(fb, nullptr, nullptr, nullptr, nullptr);      // fusion+gelu
    bgemm_kernel<4><<<dim3(VV / 64, 1, 1), 256>>>(pb, x, out, nullptr, nullptr);                 // proj+residual
}